// round 12
// baseline (speedup 1.0000x reference)
#include <cuda_runtime.h>
#include <cuda_fp16.h>
#include <math.h>
#include <stdint.h>

// Problem constants
#define Bdim 128
#define NN   1023
#define Xd   256
#define Hd   256
#define KD   512     // H + X
#define GD   1024    // 4 gates * H
#define TOTROWS 65408          // sum over levels of 128*2^l, l=0..8
// A row offset of level l: OFF(l) = 65536 - (256<<l)  (l=8 -> 0)

// ---------------------------------------------------------------------------
// Static device scratch (allocation-free rule)
// ---------------------------------------------------------------------------
__device__ __half g_ah[65536 * 512];         // A for ALL levels (64 MB)
__device__ float g_csum[2][16384 * 256];     // ping-pong c-pair-sums
__device__ float g_root[Bdim * Hd];          // root hidden state (fp32)
__device__ uint4 g_wpack[8*16*2*8*32];       // packed W, 1 MB
__device__ float g_leaf_c[Hd];
__device__ float g_leaf_h[Hd];
__device__ float g_bias[GD];                 // gate-major: [f i u o] x 256
__device__ float g_biasleaf[GD];
__device__ float g_y[Bdim*Hd];
__device__ float g_t[Bdim*Hd];
__device__ float g_z[Bdim*Hd];
__device__ int g_bar_cnt;                    // software grid barrier state
__device__ int g_bar_gen;

// Exact (setup-only) sigmoid
__device__ __forceinline__ float sigmoidf_(float x) { return 1.0f / (1.0f + expf(-x)); }

// Fast MUFU-based activations (ex2.approx + rcp.approx, rel err ~1e-6)
__device__ __forceinline__ float fast_sig(float x) {
    float e;
    asm("ex2.approx.f32 %0, %1;" : "=f"(e) : "f"(x * -1.4426950408889634f));
    float r;
    asm("rcp.approx.f32 %0, %1;" : "=f"(r) : "f"(1.0f + e));
    return r;
}
__device__ __forceinline__ float fast_tanh(float x) {
    return fmaf(2.0f, fast_sig(2.0f * x), -1.0f);
}

__device__ __forceinline__ uint32_t smem_to_u32(const void* p) {
    uint32_t a;
    asm("{ .reg .u64 t; cvta.to.shared.u64 t, %1; cvt.u32.u64 %0, t; }" : "=r"(a) : "l"(p));
    return a;
}
#define LDSM_X4(r, addr) \
    asm volatile("ldmatrix.sync.aligned.m8n8.x4.shared.b16 {%0,%1,%2,%3}, [%4];" \
        : "=r"((r)[0]), "=r"((r)[1]), "=r"((r)[2]), "=r"((r)[3]) : "r"(addr))
#define CP_ASYNC16(daddr, src) \
    asm volatile("cp.async.cg.shared.global [%0], [%1], 16;" :: "r"(daddr), "l"(src) : "memory")
#define CP_COMMIT() asm volatile("cp.async.commit_group;" ::: "memory")
#define CP_WAIT(n)  asm volatile("cp.async.wait_group %0;" :: "n"(n) : "memory")

#define MMA_F16(d, a0, a1, a2, a3, b0, b1) \
    asm volatile("mma.sync.aligned.m16n8k16.row.col.f32.f16.f16.f32 " \
        "{%0,%1,%2,%3}, {%4,%5,%6,%7}, {%8,%9}, {%0,%1,%2,%3};" \
        : "+f"((d)[0]), "+f"((d)[1]), "+f"((d)[2]), "+f"((d)[3]) \
        : "r"(a0), "r"(a1), "r"(a2), "r"(a3), "r"(b0), "r"(b1))

// GEMM geometry: tile = 64 rows x 128 interleaved cols, 128 threads (4 warps)
#define GT 128
#define K_CHUNK 32
#define STAGE_BYTES 4096
#define NSTAGE 3
#define SMEM_SZ (NSTAGE * STAGE_BYTES)  // 12288

__device__ __forceinline__ uint32_t swz_addr(uint32_t base, int row, int kb) {
    return base + row * 64 + (((((uint32_t)kb >> 4) ^ ((uint32_t)row >> 1)) & 3u) << 4) + (kb & 15);
}

__device__ __forceinline__ uint32_t pk_h2(float a, float b) {
    __half2 t = __floats2half2_rn(a, b);
    return *reinterpret_cast<uint32_t*>(&t);
}

// ---------------------------------------------------------------------------
// Software grid barrier (canonical ticket + generation pattern).
// All participating CTAs must be resident: callers use <= 256 CTAs, far under
// the residency floor (>= 2 CTAs/SM x 148 even at max regs).
// ---------------------------------------------------------------------------
__device__ __forceinline__ void gbar(int nctas, int* epoch) {
    __syncthreads();
    if (threadIdx.x == 0) {
        int target = *epoch + 1;
        __threadfence();
        int old = atomicAdd(&g_bar_cnt, 1);
        if (old == nctas - 1) {
            g_bar_cnt = 0;
            __threadfence();
            atomicExch(&g_bar_gen, target);
        } else {
            while (*(volatile int*)&g_bar_gen != target) {}
            __threadfence();
        }
        *epoch = target;
    }
    __syncthreads();
}

// ---------------------------------------------------------------------------
// setup bodies
// ---------------------------------------------------------------------------
// block 0: leaf vectors + gate-major bias + leaf bias fold (exact libm)
__device__ void leaf_all_body(int t,
                              const float* bf, const float* b_f, const float* bi, const float* b_i,
                              const float* bu, const float* b_u, const float* bo, const float* b_o,
                              const float* Wf, const float* Wi, const float* Wu, const float* Wo,
                              char* sm) {
    float* lh = (float*)sm;
    float ig = sigmoidf_(bi[t] + b_i[t]);
    float ug = tanhf(bu[t] + b_u[t]);
    float cl = ig * ug;
    g_leaf_c[t] = cl;
    float lhv = sigmoidf_(bo[t] + b_o[t]) * tanhf(cl);
    g_leaf_h[t] = lhv;
    lh[t] = 2.0f * lhv;
    float bfv = bf[t] + b_f[t];
    float biv = bi[t] + b_i[t];
    float buv = bu[t] + b_u[t];
    float bov = bo[t] + b_o[t];
    g_bias[t] = bfv; g_bias[256 + t] = biv; g_bias[512 + t] = buv; g_bias[768 + t] = bov;
    __syncthreads();
#pragma unroll
    for (int i = 0; i < 4; i++) {
        int n = i * 256 + t;             // 0..1023
        int j = n >> 2, gate = n & 3;
        const float* W = (gate == 0) ? Wf : (gate == 1) ? Wi : (gate == 2) ? Wu : Wo;
        const float* wr = W + (size_t)j * 512;
        float acc = 0.0f;
#pragma unroll 8
        for (int k = 0; k < 256; k++) acc += wr[k] * lh[k];
        float base = (gate == 0) ? bfv : (gate == 1) ? biv : (gate == 2) ? buv : bov;
        // base is this thread's bias only for j==t; read from global instead
        g_biasleaf[gate * 256 + j] = g_bias[gate * 256 + j] + acc;
        (void)base;
    }
}

__device__ void convert_w_body(int bid, int t,
                               const float* Wf, const float* Wi,
                               const float* Wu, const float* Wo) {
    int idx = bid * 256 + t;   // 0 .. 65535
    int lane = idx & 31;
    int ntp  = (idx >> 5) & 7;
    int ks   = (idx >> 8) & 1;
    int ch   = (idx >> 9) & 15;
    int cb   = idx >> 13;
    int tig = lane & 3;
    int k0 = ch * 32 + ks * 16 + tig * 2;
    uint4 v;
    uint32_t* vv = (uint32_t*)&v;
#pragma unroll
    for (int half = 0; half < 2; half++) {
        int nt = ntp * 2 + half;
        int n = cb * 128 + nt * 8 + (lane >> 2);    // interleaved n = j*4+gate
        int j = n >> 2, gate = n & 3;
        const float* W = (gate == 0) ? Wf : (gate == 1) ? Wi : (gate == 2) ? Wu : Wo;
        const float* wr = W + (size_t)j * 512;
        vv[half * 2]     = pk_h2(wr[k0],     wr[k0 + 1]);
        vv[half * 2 + 1] = pk_h2(wr[k0 + 8], wr[k0 + 9]);
    }
    g_wpack[idx] = v;
}

__device__ void embed_body(int bid, int t, const float* embed) {
    int idx = bid * 256 + t;            // 0 .. TOTROWS*64-1
    if (idx >= TOTROWS * 64) return;
    int r = idx >> 6, qq = idx & 63;
    unsigned u = 65536u - (unsigned)r;
    int l = 31 - __clz((u - 1) >> 7);   // level of row r
    int m = r - (65536 - (256 << l));
    int b = m >> l;
    int n = m & ((1 << l) - 1);
    int node0 = (2 << l) - 1 + 2 * n;
    const float4* e0 = (const float4*)(embed + ((size_t)b * NN + node0) * Xd) + qq;
    const float4* e1 = (const float4*)(embed + ((size_t)b * NN + node0 + 1) * Xd) + qq;
    float4 a = *e0, c = *e1;
    size_t p = (size_t)r * 256 + 128 + (size_t)qq * 2;
    ((__half2*)g_ah)[p]     = __floats2half2_rn(a.x + c.x, a.y + c.y);
    ((__half2*)g_ah)[p + 1] = __floats2half2_rn(a.z + c.z, a.w + c.w);
}

__global__ void setup_kernel(const float* __restrict__ embed,
                             const float* __restrict__ Wf, const float* __restrict__ Wi,
                             const float* __restrict__ Wu, const float* __restrict__ Wo,
                             const float* __restrict__ bf, const float* __restrict__ b_f,
                             const float* __restrict__ bi, const float* __restrict__ b_i,
                             const float* __restrict__ bu, const float* __restrict__ b_u,
                             const float* __restrict__ bo, const float* __restrict__ b_o) {
    extern __shared__ char sm[];
    int bid = blockIdx.x;
    if (bid == 0)           leaf_all_body(threadIdx.x, bf, b_f, bi, b_i, bu, b_u, bo, b_o,
                                          Wf, Wi, Wu, Wo, sm);
    else if (bid <= 256)    convert_w_body(bid - 1, threadIdx.x, Wf, Wi, Wu, Wo);
    else                    embed_body(bid - 257, threadIdx.x, embed);
}

// ---------------------------------------------------------------------------
// Core GEMM tile (64 rows x 128 cols) + fused epilogue. Identical math to R11.
// ---------------------------------------------------------------------------
__device__ __forceinline__ void gemm_tile(char* sm, int lvl, int leaf, int c0,
                                          int arow_off, int next_off, int cin, int cout,
                                          int cb, int rowBase) {
    const uint32_t sb = smem_to_u32(sm);
    const int tid = threadIdx.x;
    const int wid = tid >> 5, lid = tid & 31;
    const int g = lid >> 2, q = lid & 3;
    const int half = wid & 1;
    const int stripe = wid >> 1;

    const int lrow = (lid & 7) + ((lid >> 3) & 1) * 8;
    const int lkb  = (lid >> 4) * 16;

    float acc[2][8][4];
#pragma unroll
    for (int rf = 0; rf < 2; rf++)
#pragma unroll
        for (int i = 0; i < 8; i++)
#pragma unroll
            for (int k = 0; k < 4; k++) acc[rf][i][k] = 0.0f;

    const uint4* __restrict__ bsrc = g_wpack + (size_t)cb * (16 * 512)
                                   + (size_t)half * (4 * 32) + lid;

#define LOAD_A(ch) do {                                                           \
    uint32_t sb_ = sb + (uint32_t)((ch) % NSTAGE) * STAGE_BYTES;                  \
    _Pragma("unroll")                                                             \
    for (int i = tid; i < 256; i += GT) {                                         \
        int r = i >> 2, s = i & 3;                                                \
        uint32_t d = swz_addr(sb_, r, s * 16);                                    \
        const __half* srcp = g_ah + (size_t)(arow_off + rowBase + r) * KD         \
                           + (ch) * K_CHUNK + s * 8;                              \
        CP_ASYNC16(d, srcp);                                                      \
    }                                                                             \
    CP_COMMIT();                                                                  \
} while (0)

#define LOAD_B(breg, ch) do {                                                     \
    const uint4* __restrict__ bp_ = bsrc + (size_t)(ch) * 512;                    \
    _Pragma("unroll")                                                             \
    for (int ks_ = 0; ks_ < 2; ks_++)                                             \
        _Pragma("unroll")                                                         \
        for (int ntpl_ = 0; ntpl_ < 4; ntpl_++)                                   \
            (breg)[ks_ * 4 + ntpl_] = bp_[ks_ * 256 + ntpl_ * 32];                \
} while (0)

    LOAD_A(c0);
    LOAD_A(c0 + 1);
    uint4 breg[8];
    LOAD_B(breg, c0);

    for (int ch = c0; ch < 16; ch++) {
        if (ch + 1 < 16) { CP_WAIT(1); } else { CP_WAIT(0); }
        __syncthreads();
        if (ch + 2 < 16) LOAD_A(ch + 2);

        uint32_t st = sb + (uint32_t)(ch % NSTAGE) * STAGE_BYTES;
#pragma unroll
        for (int ks = 0; ks < 2; ks++) {
            int kb = ks * 32;
            uint32_t af[2][4];
#pragma unroll
            for (int rf = 0; rf < 2; rf++) {
                int r = stripe * 32 + rf * 16 + lrow;
                LDSM_X4(af[rf], swz_addr(st, r, kb + lkb));
            }
#pragma unroll
            for (int ntpl = 0; ntpl < 4; ntpl++) {
                uint4 bb = breg[ks * 4 + ntpl];
#pragma unroll
                for (int rf = 0; rf < 2; rf++) {
                    MMA_F16(acc[rf][ntpl * 2],     af[rf][0], af[rf][1], af[rf][2], af[rf][3], bb.x, bb.y);
                    MMA_F16(acc[rf][ntpl * 2 + 1], af[rf][0], af[rf][1], af[rf][2], af[rf][3], bb.z, bb.w);
                }
            }
        }
        if (ch + 1 < 16) LOAD_B(breg, ch + 1);
    }
#undef LOAD_A
#undef LOAD_B

    const bool evenq = ((q & 1) == 0);
    const float* bp = leaf ? g_biasleaf : g_bias;
    const float* csin = g_csum[cin];
    float* csout = g_csum[cout];
    const int jb = cb * 32 + half * 16 + (q >> 1);
    const bool geven = ((g & 1) == 0);
#pragma unroll
    for (int rf = 0; rf < 2; rf++) {
        const int m = rowBase + stripe * 32 + rf * 16 + g + ((lid & 1) ? 8 : 0);
        const float* csrow = csin + (size_t)m * 256;
        int m2 = 0;
        if (lvl > 0) {
            int b = m >> lvl;
            int n = m & ((1 << lvl) - 1);
            m2 = (b << (lvl - 1)) + (n >> 1);
        }
#pragma unroll
        for (int nt = 0; nt < 8; nt++) {
            float t0 = __shfl_xor_sync(0xffffffffu, acc[rf][nt][0], 1);
            float t1 = __shfl_xor_sync(0xffffffffu, acc[rf][nt][1], 1);
            float t2 = __shfl_xor_sync(0xffffffffu, acc[rf][nt][2], 1);
            float t3 = __shfl_xor_sync(0xffffffffu, acc[rf][nt][3], 1);
            float pf = evenq ? acc[rf][nt][0] : t2;
            float pi = evenq ? acc[rf][nt][1] : t3;
            float pu = evenq ? t0 : acc[rf][nt][2];
            float po = evenq ? t1 : acc[rf][nt][3];
            int j = jb + nt * 2;
            float f  = fast_sig (pf + bp[j]);
            float ig = fast_sig (pi + bp[256 + j]);
            float u  = fast_tanh(pu + bp[512 + j]);
            float o  = fast_sig (po + bp[768 + j]);
            float csum = leaf ? 2.0f * g_leaf_c[j] : csrow[j];
            float cn = ig * u + f * csum;
            float hn = o * fast_tanh(cn);
            if (lvl > 0) {
                float cnp = __shfl_down_sync(0xffffffffu, cn, 4);
                float hnp = __shfl_down_sync(0xffffffffu, hn, 4);
                if (geven) {
                    g_ah[(size_t)(next_off + m2) * KD + j] = __float2half(hn + hnp);
                    csout[(size_t)m2 * 256 + j] = cn + cnp;
                }
            } else {
                g_root[m * 256 + j] = hn;
            }
        }
    }
}

// Standalone GEMM kernel for big levels (l = 8..5)
__global__ void __launch_bounds__(GT) gemm_hmma_kernel(int lvl, int leaf, int c0,
                                                       int arow_off, int next_off,
                                                       int cin, int cout) {
    extern __shared__ char sm[];
    gemm_tile(sm, lvl, leaf, c0, arow_off, next_off, cin, cout,
              blockIdx.x, blockIdx.y * 64);
}

// ---------------------------------------------------------------------------
// Head body (128 threads, one batch row): O[b] = act(A[b] @ W^T + bias [+ add])
// ---------------------------------------------------------------------------
__device__ void head_body(char* sm, const float* __restrict__ A,
                          const float* __restrict__ W, const float* __restrict__ bias,
                          const float* __restrict__ addv, int act,
                          float* __restrict__ O, int b) {
    float* arow = (float*)sm;
    int t = threadIdx.x;
    arow[t]       = A[b * 256 + t];
    arow[t + 128] = A[b * 256 + t + 128];
    __syncthreads();
#pragma unroll
    for (int jj = 0; jj < 2; jj++) {
        int j = t + jj * 128;
        float acc = bias[j];
        const float* wr = W + (size_t)j * 256;
#pragma unroll 8
        for (int k = 0; k < 256; k++) acc += arow[k] * wr[k];
        if (addv) acc += addv[b * 256 + j];
        if (act == 1) acc = fast_tanh(acc);
        else if (act == 2) acc = fmaxf(acc, 0.0f);
        O[b * 256 + j] = acc;
    }
    __syncthreads();
}

// ---------------------------------------------------------------------------
// Persistent tail: levels 4..0 + head MLP, one launch, software grid barrier.
// Grid = 256 CTAs x 128 threads (always fully resident).
// ---------------------------------------------------------------------------
__global__ void __launch_bounds__(GT) tail_kernel(
        const float* __restrict__ W1, const float* __restrict__ bl1,
        const float* __restrict__ W2, const float* __restrict__ bl2,
        const float* __restrict__ W3, const float* __restrict__ bl3,
        const float* __restrict__ W4, const float* __restrict__ bl4,
        float* __restrict__ out) {
    extern __shared__ char sm[];
    const int cta = blockIdx.x;
    int epoch = 0;
    if (threadIdx.x == 0) epoch = *(volatile int*)&g_bar_gen;

    for (int l = 4; l >= 0; --l) {
        int ntiles = 16 << l;                 // 8 colblks * 2*2^l rowblks
        if (cta < ntiles) {
            int arow_off = 65536 - (256 << l);
            int next_off = (l > 0) ? (65536 - (128 << l)) : 0;
            int cout = (8 - l) & 1;
            gemm_tile(sm, l, 0, 0, arow_off, next_off, cout ^ 1, cout,
                      cta & 7, (cta >> 3) * 64);
        }
        gbar(256, &epoch);
    }
    // Heads: H1 y & t, H2 z, H3 out
    if (cta < 128) head_body(sm, g_root, W1, bl1, nullptr, 1, g_y, cta);
    else           head_body(sm, g_root, W2, bl2, nullptr, 2, g_t, cta - 128);
    gbar(256, &epoch);
    if (cta < 128) head_body(sm, g_t, W3, bl3, g_y, 0, g_z, cta);
    gbar(256, &epoch);
    if (cta < 128) head_body(sm, g_z, W4, bl4, nullptr, 2, out, cta);
}

// ---------------------------------------------------------------------------
extern "C" void kernel_launch(void* const* d_in, const int* in_sizes, int n_in,
                              void* d_out, int out_size) {
    const float* embed = (const float*)d_in[0];
    const float* Wf  = (const float*)d_in[1];
    const float* bf  = (const float*)d_in[2];
    const float* b_f = (const float*)d_in[3];
    const float* Wi  = (const float*)d_in[4];
    const float* bi  = (const float*)d_in[5];
    const float* b_i = (const float*)d_in[6];
    const float* Wu  = (const float*)d_in[7];
    const float* bu  = (const float*)d_in[8];
    const float* b_u = (const float*)d_in[9];
    const float* Wo  = (const float*)d_in[10];
    const float* bo  = (const float*)d_in[11];
    const float* b_o = (const float*)d_in[12];
    const float* W1  = (const float*)d_in[13];
    const float* bl1 = (const float*)d_in[14];
    const float* W2  = (const float*)d_in[15];
    const float* bl2 = (const float*)d_in[16];
    const float* W3  = (const float*)d_in[17];
    const float* bl3 = (const float*)d_in[18];
    const float* W4  = (const float*)d_in[19];
    const float* bl4 = (const float*)d_in[20];
    float* out = (float*)d_out;

    int setup_blocks = 257 + (TOTROWS * 64 + 255) / 256;
    setup_kernel<<<setup_blocks, 256, 1024>>>(embed, Wf, Wi, Wu, Wo,
                                              bf, b_f, bi, b_i, bu, b_u, bo, b_o);

    for (int l = 8; l >= 5; --l) {
        int M = Bdim << l;
        int leaf = (l == 8);
        int arow_off = 65536 - (256 << l);
        int next_off = 65536 - (128 << l);
        int cout = (8 - l) & 1;
        gemm_hmma_kernel<<<dim3(8, M / 64), GT, SMEM_SZ>>>(
            l, leaf, leaf ? 8 : 0, arow_off, next_off, cout ^ 1, cout);
    }

    tail_kernel<<<256, GT, SMEM_SZ>>>(W1, bl1, W2, bl2, W3, bl3, W4, bl4, out);
}

// round 13
// speedup vs baseline: 1.0374x; 1.0374x over previous
#include <cuda_runtime.h>
#include <cuda_fp16.h>
#include <math.h>
#include <stdint.h>

// Problem constants
#define Bdim 128
#define NN   1023
#define Xd   256
#define Hd   256
#define KD   512     // H + X
#define GD   1024    // 4 gates * H
#define TOTROWS 65408          // sum over levels of 128*2^l, l=0..8
// A row offset of level l: OFF(l) = 65536 - (256<<l)  (l=8 -> 0)

// ---------------------------------------------------------------------------
// Static device scratch (allocation-free rule)
// ---------------------------------------------------------------------------
__device__ __half g_ah[65536 * 512];         // A for ALL levels (64 MB)
__device__ float g_csum[2][16384 * 256];     // ping-pong c-pair-sums
__device__ float g_root[Bdim * Hd];          // root hidden state (fp32)
__device__ uint4 g_wpack[8*16*2*8*32];       // packed W, 1 MB
__device__ float g_leaf_c[Hd];
__device__ float g_leaf_h[Hd];
__device__ float g_bias[GD];                 // gate-major: [f i u o] x 256
__device__ float g_biasleaf[GD];
__device__ float g_y[Bdim*Hd];
__device__ float g_t[Bdim*Hd];
__device__ float g_z[Bdim*Hd];

// Exact (setup-only) sigmoid
__device__ __forceinline__ float sigmoidf_(float x) { return 1.0f / (1.0f + expf(-x)); }

// Fast MUFU-based activations (ex2.approx + rcp.approx, rel err ~1e-6)
__device__ __forceinline__ float fast_sig(float x) {
    float e;
    asm("ex2.approx.f32 %0, %1;" : "=f"(e) : "f"(x * -1.4426950408889634f));
    float r;
    asm("rcp.approx.f32 %0, %1;" : "=f"(r) : "f"(1.0f + e));
    return r;
}
__device__ __forceinline__ float fast_tanh(float x) {
    return fmaf(2.0f, fast_sig(2.0f * x), -1.0f);
}

__device__ __forceinline__ uint32_t smem_to_u32(const void* p) {
    uint32_t a;
    asm("{ .reg .u64 t; cvta.to.shared.u64 t, %1; cvt.u32.u64 %0, t; }" : "=r"(a) : "l"(p));
    return a;
}
#define LDSM_X4(r, addr) \
    asm volatile("ldmatrix.sync.aligned.m8n8.x4.shared.b16 {%0,%1,%2,%3}, [%4];" \
        : "=r"((r)[0]), "=r"((r)[1]), "=r"((r)[2]), "=r"((r)[3]) : "r"(addr))
#define CP_ASYNC16(daddr, src) \
    asm volatile("cp.async.cg.shared.global [%0], [%1], 16;" :: "r"(daddr), "l"(src) : "memory")
#define CP_COMMIT() asm volatile("cp.async.commit_group;" ::: "memory")
#define CP_WAIT(n)  asm volatile("cp.async.wait_group %0;" :: "n"(n) : "memory")

#define MMA_F16(d, a0, a1, a2, a3, b0, b1) \
    asm volatile("mma.sync.aligned.m16n8k16.row.col.f32.f16.f16.f32 " \
        "{%0,%1,%2,%3}, {%4,%5,%6,%7}, {%8,%9}, {%0,%1,%2,%3};" \
        : "+f"((d)[0]), "+f"((d)[1]), "+f"((d)[2]), "+f"((d)[3]) \
        : "r"(a0), "r"(a1), "r"(a2), "r"(a3), "r"(b0), "r"(b1))

// GEMM geometry: CTA = 64 rows x 128 interleaved cols, 128 threads (4 warps)
#define GT 128
#define K_CHUNK 32
#define STAGE_BYTES 4096
#define NSTAGE 3
#define SMEM_SZ (NSTAGE * STAGE_BYTES)  // 12288

__device__ __forceinline__ uint32_t swz_addr(uint32_t base, int row, int kb) {
    return base + row * 64 + (((((uint32_t)kb >> 4) ^ ((uint32_t)row >> 1)) & 3u) << 4) + (kb & 15);
}

__device__ __forceinline__ uint32_t pk_h2(float a, float b) {
    __half2 t = __floats2half2_rn(a, b);
    return *reinterpret_cast<uint32_t*>(&t);
}

// ---------------------------------------------------------------------------
// setup bodies (single launch)
// ---------------------------------------------------------------------------
// block 0: leaf vectors + gate-major bias + leaf bias fold (exact libm)
__device__ void leaf_all_body(int t,
                              const float* bf, const float* b_f, const float* bi, const float* b_i,
                              const float* bu, const float* b_u, const float* bo, const float* b_o,
                              const float* Wf, const float* Wi, const float* Wu, const float* Wo,
                              char* sm) {
    float* lh = (float*)sm;
    float ig = sigmoidf_(bi[t] + b_i[t]);
    float ug = tanhf(bu[t] + b_u[t]);
    float cl = ig * ug;
    g_leaf_c[t] = cl;
    float lhv = sigmoidf_(bo[t] + b_o[t]) * tanhf(cl);
    g_leaf_h[t] = lhv;
    lh[t] = 2.0f * lhv;
    g_bias[t]       = bf[t] + b_f[t];
    g_bias[256 + t] = bi[t] + b_i[t];
    g_bias[512 + t] = bu[t] + b_u[t];
    g_bias[768 + t] = bo[t] + b_o[t];
    __syncthreads();
#pragma unroll
    for (int i = 0; i < 4; i++) {
        int n = i * 256 + t;             // 0..1023
        int j = n >> 2, gate = n & 3;
        const float* W = (gate == 0) ? Wf : (gate == 1) ? Wi : (gate == 2) ? Wu : Wo;
        const float* wr = W + (size_t)j * 512;
        float acc = 0.0f;
#pragma unroll 8
        for (int k = 0; k < 256; k++) acc += wr[k] * lh[k];
        g_biasleaf[gate * 256 + j] = g_bias[gate * 256 + j] + acc;
    }
}

__device__ void convert_w_body(int bid, int t,
                               const float* Wf, const float* Wi,
                               const float* Wu, const float* Wo) {
    int idx = bid * 256 + t;   // 0 .. 65535
    int lane = idx & 31;
    int ntp  = (idx >> 5) & 7;
    int ks   = (idx >> 8) & 1;
    int ch   = (idx >> 9) & 15;
    int cb   = idx >> 13;
    int tig = lane & 3;
    int k0 = ch * 32 + ks * 16 + tig * 2;
    uint4 v;
    uint32_t* vv = (uint32_t*)&v;
#pragma unroll
    for (int half = 0; half < 2; half++) {
        int nt = ntp * 2 + half;
        int n = cb * 128 + nt * 8 + (lane >> 2);    // interleaved n = j*4+gate
        int j = n >> 2, gate = n & 3;
        const float* W = (gate == 0) ? Wf : (gate == 1) ? Wi : (gate == 2) ? Wu : Wo;
        const float* wr = W + (size_t)j * 512;
        vv[half * 2]     = pk_h2(wr[k0],     wr[k0 + 1]);
        vv[half * 2 + 1] = pk_h2(wr[k0 + 8], wr[k0 + 9]);
    }
    g_wpack[idx] = v;
}

__device__ void embed_body(int bid, int t, const float* embed) {
    int idx = bid * 256 + t;            // 0 .. TOTROWS*64-1
    if (idx >= TOTROWS * 64) return;
    int r = idx >> 6, qq = idx & 63;
    unsigned u = 65536u - (unsigned)r;
    int l = 31 - __clz((u - 1) >> 7);   // level of row r
    int m = r - (65536 - (256 << l));
    int b = m >> l;
    int n = m & ((1 << l) - 1);
    int node0 = (2 << l) - 1 + 2 * n;
    const float4* e0 = (const float4*)(embed + ((size_t)b * NN + node0) * Xd) + qq;
    const float4* e1 = (const float4*)(embed + ((size_t)b * NN + node0 + 1) * Xd) + qq;
    float4 a = *e0, c = *e1;
    size_t p = (size_t)r * 256 + 128 + (size_t)qq * 2;
    ((__half2*)g_ah)[p]     = __floats2half2_rn(a.x + c.x, a.y + c.y);
    ((__half2*)g_ah)[p + 1] = __floats2half2_rn(a.z + c.z, a.w + c.w);
}

__global__ void setup_kernel(const float* __restrict__ embed,
                             const float* __restrict__ Wf, const float* __restrict__ Wi,
                             const float* __restrict__ Wu, const float* __restrict__ Wo,
                             const float* __restrict__ bf, const float* __restrict__ b_f,
                             const float* __restrict__ bi, const float* __restrict__ b_i,
                             const float* __restrict__ bu, const float* __restrict__ b_u,
                             const float* __restrict__ bo, const float* __restrict__ b_o) {
    extern __shared__ char sm[];
    int bid = blockIdx.x;
    if (bid == 0)           leaf_all_body(threadIdx.x, bf, b_f, bi, b_i, bu, b_u, bo, b_o,
                                          Wf, Wi, Wu, Wo, sm);
    else if (bid <= 256)    convert_w_body(bid - 1, threadIdx.x, Wf, Wi, Wu, Wo);
    else                    embed_body(bid - 257, threadIdx.x, embed);
}

// ---------------------------------------------------------------------------
// HMMA GEMM + fully fused epilogue (MUFU fast activations). R11-identical.
// ---------------------------------------------------------------------------
__global__ void __launch_bounds__(GT) gemm_hmma_kernel(int lvl, int leaf, int c0,
                                                       int arow_off, int next_off,
                                                       int cin, int cout) {
    extern __shared__ char sm[];
    const uint32_t sb = smem_to_u32(sm);
    const int tid = threadIdx.x;
    const int wid = tid >> 5, lid = tid & 31;
    const int g = lid >> 2, q = lid & 3;
    const int half = wid & 1;            // column half (64 cols)
    const int stripe = wid >> 1;         // row stripe (32 rows)
    const int rowBase = blockIdx.y * 64;
    const int cb = blockIdx.x;           // colblk: 128 interleaved n

    const int lrow = (lid & 7) + ((lid >> 3) & 1) * 8;
    const int lkb  = (lid >> 4) * 16;

    float acc[2][8][4];
#pragma unroll
    for (int rf = 0; rf < 2; rf++)
#pragma unroll
        for (int i = 0; i < 8; i++)
#pragma unroll
            for (int k = 0; k < 4; k++) acc[rf][i][k] = 0.0f;

    const uint4* __restrict__ bsrc = g_wpack + (size_t)cb * (16 * 512)
                                   + (size_t)half * (4 * 32) + lid;

#define LOAD_A(ch) do {                                                           \
    uint32_t sb_ = sb + (uint32_t)((ch) % NSTAGE) * STAGE_BYTES;                  \
    _Pragma("unroll")                                                             \
    for (int i = tid; i < 256; i += GT) {                                         \
        int r = i >> 2, s = i & 3;                                                \
        uint32_t d = swz_addr(sb_, r, s * 16);                                    \
        const __half* srcp = g_ah + (size_t)(arow_off + rowBase + r) * KD         \
                           + (ch) * K_CHUNK + s * 8;                              \
        CP_ASYNC16(d, srcp);                                                      \
    }                                                                             \
    CP_COMMIT();                                                                  \
} while (0)

#define LOAD_B(breg, ch) do {                                                     \
    const uint4* __restrict__ bp_ = bsrc + (size_t)(ch) * 512;                    \
    _Pragma("unroll")                                                             \
    for (int ks_ = 0; ks_ < 2; ks_++)                                             \
        _Pragma("unroll")                                                         \
        for (int ntpl_ = 0; ntpl_ < 4; ntpl_++)                                   \
            (breg)[ks_ * 4 + ntpl_] = bp_[ks_ * 256 + ntpl_ * 32];                \
} while (0)

    LOAD_A(c0);
    LOAD_A(c0 + 1);
    uint4 breg[8];
    LOAD_B(breg, c0);

    for (int ch = c0; ch < 16; ch++) {
        if (ch + 1 < 16) { CP_WAIT(1); } else { CP_WAIT(0); }
        __syncthreads();
        if (ch + 2 < 16) LOAD_A(ch + 2);

        uint32_t st = sb + (uint32_t)(ch % NSTAGE) * STAGE_BYTES;
#pragma unroll
        for (int ks = 0; ks < 2; ks++) {
            int kb = ks * 32;
            uint32_t af[2][4];
#pragma unroll
            for (int rf = 0; rf < 2; rf++) {
                int r = stripe * 32 + rf * 16 + lrow;
                LDSM_X4(af[rf], swz_addr(st, r, kb + lkb));
            }
#pragma unroll
            for (int ntpl = 0; ntpl < 4; ntpl++) {
                uint4 bb = breg[ks * 4 + ntpl];
#pragma unroll
                for (int rf = 0; rf < 2; rf++) {
                    MMA_F16(acc[rf][ntpl * 2],     af[rf][0], af[rf][1], af[rf][2], af[rf][3], bb.x, bb.y);
                    MMA_F16(acc[rf][ntpl * 2 + 1], af[rf][0], af[rf][1], af[rf][2], af[rf][3], bb.z, bb.w);
                }
            }
        }
        if (ch + 1 < 16) LOAD_B(breg, ch + 1);
    }
#undef LOAD_A
#undef LOAD_B

    // Fused epilogue: gates -> (h, c); sibling pair-sum via shfl_down(4);
    // even-g lanes write next level's A h-half (fp16) + c-sum (fp32).
    const bool evenq = ((q & 1) == 0);
    const float* bp = leaf ? g_biasleaf : g_bias;
    const float* csin = g_csum[cin];
    float* csout = g_csum[cout];
    const int jb = cb * 32 + half * 16 + (q >> 1);
    const bool geven = ((g & 1) == 0);
#pragma unroll
    for (int rf = 0; rf < 2; rf++) {
        const int m = rowBase + stripe * 32 + rf * 16 + g + ((lid & 1) ? 8 : 0);
        const float* csrow = csin + (size_t)m * 256;
        int m2 = 0;
        if (lvl > 0) {
            int b = m >> lvl;
            int n = m & ((1 << lvl) - 1);
            m2 = (b << (lvl - 1)) + (n >> 1);
        }
#pragma unroll
        for (int nt = 0; nt < 8; nt++) {
            float t0 = __shfl_xor_sync(0xffffffffu, acc[rf][nt][0], 1);
            float t1 = __shfl_xor_sync(0xffffffffu, acc[rf][nt][1], 1);
            float t2 = __shfl_xor_sync(0xffffffffu, acc[rf][nt][2], 1);
            float t3 = __shfl_xor_sync(0xffffffffu, acc[rf][nt][3], 1);
            float pf = evenq ? acc[rf][nt][0] : t2;
            float pi = evenq ? acc[rf][nt][1] : t3;
            float pu = evenq ? t0 : acc[rf][nt][2];
            float po = evenq ? t1 : acc[rf][nt][3];
            int j = jb + nt * 2;
            float f  = fast_sig (pf + bp[j]);
            float ig = fast_sig (pi + bp[256 + j]);
            float u  = fast_tanh(pu + bp[512 + j]);
            float o  = fast_sig (po + bp[768 + j]);
            float csum = leaf ? 2.0f * g_leaf_c[j] : csrow[j];
            float cn = ig * u + f * csum;
            float hn = o * fast_tanh(cn);
            if (lvl > 0) {
                float cnp = __shfl_down_sync(0xffffffffu, cn, 4);
                float hnp = __shfl_down_sync(0xffffffffu, hn, 4);
                if (geven) {
                    g_ah[(size_t)(next_off + m2) * KD + j] = __float2half(hn + hnp);
                    csout[(size_t)m2 * 256 + j] = cn + cnp;
                }
            } else {
                g_root[m * 256 + j] = hn;
            }
        }
    }
}

// ---------------------------------------------------------------------------
// Head MLP (tiny, fp32): out = act(A @ W^T + bias [+ g_y])
// ---------------------------------------------------------------------------
__global__ void head_kernel(const float* __restrict__ W, const float* __restrict__ bias,
                            int src, int dst, int addy, int act, float* __restrict__ out) {
    __shared__ float arow[256];
    int b = blockIdx.x;
    int j = threadIdx.x;
    const float* A = (src == 0) ? g_root : (src == 1) ? g_t : g_z;
    arow[j] = A[b * 256 + j];
    __syncthreads();
    float acc = bias[j];
    const float* wr = W + j * 256;
#pragma unroll 8
    for (int k = 0; k < 256; k++) acc += arow[k] * wr[k];
    if (addy) acc += g_y[b * 256 + j];
    if (act == 1) acc = fast_tanh(acc);
    else if (act == 2) acc = fmaxf(acc, 0.0f);
    float* O = (dst == 0) ? g_y : (dst == 1) ? g_t : (dst == 2) ? g_z : out;
    O[b * 256 + j] = acc;
}

// Dual head: blocks 0..127 -> y = tanh(root@W1^T+bl1); 128..255 -> t = relu(root@W2^T+bl2)
__global__ void head_dual_kernel(const float* __restrict__ W1, const float* __restrict__ bl1,
                                 const float* __restrict__ W2, const float* __restrict__ bl2) {
    __shared__ float arow[256];
    int blk = blockIdx.x;
    int b = blk & 127;
    int second = blk >> 7;
    int j = threadIdx.x;
    arow[j] = g_root[b * 256 + j];
    __syncthreads();
    const float* W = second ? W2 : W1;
    const float* bias = second ? bl2 : bl1;
    float acc = bias[j];
    const float* wr = W + j * 256;
#pragma unroll 8
    for (int k = 0; k < 256; k++) acc += arow[k] * wr[k];
    if (second) {
        g_t[b * 256 + j] = fmaxf(acc, 0.0f);
    } else {
        g_y[b * 256 + j] = fast_tanh(acc);
    }
}

// ---------------------------------------------------------------------------
extern "C" void kernel_launch(void* const* d_in, const int* in_sizes, int n_in,
                              void* d_out, int out_size) {
    const float* embed = (const float*)d_in[0];
    const float* Wf  = (const float*)d_in[1];
    const float* bf  = (const float*)d_in[2];
    const float* b_f = (const float*)d_in[3];
    const float* Wi  = (const float*)d_in[4];
    const float* bi  = (const float*)d_in[5];
    const float* b_i = (const float*)d_in[6];
    const float* Wu  = (const float*)d_in[7];
    const float* bu  = (const float*)d_in[8];
    const float* b_u = (const float*)d_in[9];
    const float* Wo  = (const float*)d_in[10];
    const float* bo  = (const float*)d_in[11];
    const float* b_o = (const float*)d_in[12];
    const float* W1  = (const float*)d_in[13];
    const float* bl1 = (const float*)d_in[14];
    const float* W2  = (const float*)d_in[15];
    const float* bl2 = (const float*)d_in[16];
    const float* W3  = (const float*)d_in[17];
    const float* bl3 = (const float*)d_in[18];
    const float* W4  = (const float*)d_in[19];
    const float* bl4 = (const float*)d_in[20];
    float* out = (float*)d_out;

    int setup_blocks = 257 + (TOTROWS * 64 + 255) / 256;
    setup_kernel<<<setup_blocks, 256, 1024>>>(embed, Wf, Wi, Wu, Wo,
                                              bf, b_f, bi, b_i, bu, b_u, bo, b_o);

    for (int l = 8; l >= 0; --l) {
        int M = Bdim << l;
        int leaf = (l == 8);
        int arow_off = 65536 - (256 << l);
        int next_off = (l > 0) ? (65536 - (128 << l)) : 0;
        int cout = (8 - l) & 1;
        int cin = cout ^ 1;
        gemm_hmma_kernel<<<dim3(8, M / 64), GT, SMEM_SZ>>>(
            l, leaf, leaf ? 8 : 0, arow_off, next_off, cin, cout);
    }

    head_dual_kernel<<<256, 256>>>(W1, bl1, W2, bl2);          // y, t
    head_kernel<<<128, 256>>>(W3, bl3, 1, 2, 1, 0, out);       // z = t@W3^T+bl3+y
    head_kernel<<<128, 256>>>(W4, bl4, 2, 3, 0, 2, out);       // out = relu(z@W4^T+bl4)
}

// round 14
// speedup vs baseline: 1.2212x; 1.1772x over previous
#include <cuda_runtime.h>
#include <cuda_fp16.h>
#include <math.h>
#include <stdint.h>

// Problem constants
#define Bdim 128
#define NN   1023
#define Xd   256
#define Hd   256
#define KD   512     // H + X
#define GD   1024    // 4 gates * H
#define TOTROWS 65408          // sum over levels of 128*2^l, l=0..8
// A row offset of level l: OFF(l) = 65536 - (256<<l)  (l=8 -> 0)

// ---------------------------------------------------------------------------
// Static device scratch (allocation-free rule)
// ---------------------------------------------------------------------------
__device__ __half g_ah[65536 * 512];         // A for ALL levels (64 MB)
__device__ float g_csum[2][16384 * 256];     // ping-pong c-pair-sums
__device__ float g_root[Bdim * Hd];          // root hidden state (fp32)
__device__ uint4 g_wpack[8*16*2*8*32];       // packed W, 1 MB
__device__ float g_leaf_c[Hd];
__device__ float g_leaf_h[Hd];
__device__ float g_bias[GD];                 // gate-major: [f i u o] x 256
__device__ float g_biasleaf[GD];
__device__ float g_y[Bdim*Hd];
__device__ float g_t[Bdim*Hd];
__device__ float g_z[Bdim*Hd];

// Exact (setup-only) sigmoid
__device__ __forceinline__ float sigmoidf_(float x) { return 1.0f / (1.0f + expf(-x)); }

// Fast MUFU-based activations (ex2.approx + rcp.approx, rel err ~1e-6)
__device__ __forceinline__ float fast_sig(float x) {
    float e;
    asm("ex2.approx.f32 %0, %1;" : "=f"(e) : "f"(x * -1.4426950408889634f));
    float r;
    asm("rcp.approx.f32 %0, %1;" : "=f"(r) : "f"(1.0f + e));
    return r;
}
__device__ __forceinline__ float fast_tanh(float x) {
    return fmaf(2.0f, fast_sig(2.0f * x), -1.0f);
}

__device__ __forceinline__ uint32_t smem_to_u32(const void* p) {
    uint32_t a;
    asm("{ .reg .u64 t; cvta.to.shared.u64 t, %1; cvt.u32.u64 %0, t; }" : "=r"(a) : "l"(p));
    return a;
}
#define LDSM_X4(r, addr) \
    asm volatile("ldmatrix.sync.aligned.m8n8.x4.shared.b16 {%0,%1,%2,%3}, [%4];" \
        : "=r"((r)[0]), "=r"((r)[1]), "=r"((r)[2]), "=r"((r)[3]) : "r"(addr))
#define CP_ASYNC16(daddr, src) \
    asm volatile("cp.async.cg.shared.global [%0], [%1], 16;" :: "r"(daddr), "l"(src) : "memory")
#define CP_COMMIT() asm volatile("cp.async.commit_group;" ::: "memory")
#define CP_WAIT(n)  asm volatile("cp.async.wait_group %0;" :: "n"(n) : "memory")

#define MMA_F16(d, a0, a1, a2, a3, b0, b1) \
    asm volatile("mma.sync.aligned.m16n8k16.row.col.f32.f16.f16.f32 " \
        "{%0,%1,%2,%3}, {%4,%5,%6,%7}, {%8,%9}, {%0,%1,%2,%3};" \
        : "+f"((d)[0]), "+f"((d)[1]), "+f"((d)[2]), "+f"((d)[3]) \
        : "r"(a0), "r"(a1), "r"(a2), "r"(a3), "r"(b0), "r"(b1))

// GEMM geometry: CTA = 64 rows x 128 interleaved cols, 128 threads (4 warps)
#define GT 128
#define K_CHUNK 32
#define STAGE_BYTES 4096
#define NSTAGE 4
#define SMEM_SZ (NSTAGE * STAGE_BYTES)  // 16384

__device__ __forceinline__ uint32_t swz_addr(uint32_t base, int row, int kb) {
    return base + row * 64 + (((((uint32_t)kb >> 4) ^ ((uint32_t)row >> 1)) & 3u) << 4) + (kb & 15);
}

__device__ __forceinline__ uint32_t pk_h2(float a, float b) {
    __half2 t = __floats2half2_rn(a, b);
    return *reinterpret_cast<uint32_t*>(&t);
}

// ---------------------------------------------------------------------------
// k0: leaf vectors + gate-major combined bias (exact libm; runs once)
// ---------------------------------------------------------------------------
__global__ void leaf_bias_kernel(const float* __restrict__ bf, const float* __restrict__ b_f,
                                 const float* __restrict__ bi, const float* __restrict__ b_i,
                                 const float* __restrict__ bu, const float* __restrict__ b_u,
                                 const float* __restrict__ bo, const float* __restrict__ b_o) {
    int j = threadIdx.x;
    float ig = sigmoidf_(bi[j] + b_i[j]);
    float ug = tanhf(bu[j] + b_u[j]);
    float cl = ig * ug;
    g_leaf_c[j] = cl;
    g_leaf_h[j] = sigmoidf_(bo[j] + b_o[j]) * tanhf(cl);
    g_bias[j]       = bf[j] + b_f[j];
    g_bias[256 + j] = bi[j] + b_i[j];
    g_bias[512 + j] = bu[j] + b_u[j];
    g_bias[768 + j] = bo[j] + b_o[j];
}

// ---------------------------------------------------------------------------
// k1: leaf bias fold (fp32 exact)
// ---------------------------------------------------------------------------
__global__ void leafdot_kernel(const float* __restrict__ Wf, const float* __restrict__ Wi,
                               const float* __restrict__ Wu, const float* __restrict__ Wo) {
    __shared__ float lh[256];
    int t = threadIdx.x;
    lh[t] = 2.0f * g_leaf_h[t];
    __syncthreads();
    int n = blockIdx.x * 256 + t;     // 0..1023
    int j = n >> 2, gate = n & 3;
    const float* W = (gate == 0) ? Wf : (gate == 1) ? Wi : (gate == 2) ? Wu : Wo;
    const float* wr = W + (size_t)j * 512;
    float acc = 0.0f;
#pragma unroll 8
    for (int k = 0; k < 256; k++) acc += wr[k] * lh[k];
    g_biasleaf[gate * 256 + j] = g_bias[gate * 256 + j] + acc;
}

// ---------------------------------------------------------------------------
// k2: fused convert_w (blocks 0..255) + embed halves for ALL levels
// ---------------------------------------------------------------------------
__device__ void convert_w_body(int bid, int t,
                               const float* Wf, const float* Wi,
                               const float* Wu, const float* Wo) {
    int idx = bid * 256 + t;   // 0 .. 65535
    int lane = idx & 31;
    int ntp  = (idx >> 5) & 7;
    int ks   = (idx >> 8) & 1;
    int ch   = (idx >> 9) & 15;
    int cb   = idx >> 13;
    int tig = lane & 3;
    int k0 = ch * 32 + ks * 16 + tig * 2;
    uint4 v;
    uint32_t* vv = (uint32_t*)&v;
#pragma unroll
    for (int half = 0; half < 2; half++) {
        int nt = ntp * 2 + half;
        int n = cb * 128 + nt * 8 + (lane >> 2);    // interleaved n = j*4+gate
        int j = n >> 2, gate = n & 3;
        const float* W = (gate == 0) ? Wf : (gate == 1) ? Wi : (gate == 2) ? Wu : Wo;
        const float* wr = W + (size_t)j * 512;
        vv[half * 2]     = pk_h2(wr[k0],     wr[k0 + 1]);
        vv[half * 2 + 1] = pk_h2(wr[k0 + 8], wr[k0 + 9]);
    }
    g_wpack[idx] = v;
}

__device__ void embed_body(int bid, int t, const float* embed) {
    int idx = bid * 256 + t;            // 0 .. TOTROWS*64-1
    if (idx >= TOTROWS * 64) return;
    int r = idx >> 6, qq = idx & 63;
    unsigned u = 65536u - (unsigned)r;
    int l = 31 - __clz((u - 1) >> 7);   // level of row r
    int m = r - (65536 - (256 << l));
    int b = m >> l;
    int n = m & ((1 << l) - 1);
    int node0 = (2 << l) - 1 + 2 * n;
    const float4* e0 = (const float4*)(embed + ((size_t)b * NN + node0) * Xd) + qq;
    const float4* e1 = (const float4*)(embed + ((size_t)b * NN + node0 + 1) * Xd) + qq;
    float4 a = *e0, c = *e1;
    size_t p = (size_t)r * 256 + 128 + (size_t)qq * 2;
    ((__half2*)g_ah)[p]     = __floats2half2_rn(a.x + c.x, a.y + c.y);
    ((__half2*)g_ah)[p + 1] = __floats2half2_rn(a.z + c.z, a.w + c.w);
}

__global__ void setup_kernel(const float* __restrict__ embed,
                             const float* __restrict__ Wf, const float* __restrict__ Wi,
                             const float* __restrict__ Wu, const float* __restrict__ Wo) {
    int bid = blockIdx.x;
    if (bid < 256) convert_w_body(bid, threadIdx.x, Wf, Wi, Wu, Wo);
    else           embed_body(bid - 256, threadIdx.x, embed);
}

// ---------------------------------------------------------------------------
// HMMA GEMM + fully fused epilogue (MUFU fast activations).
// R11 mainloop with deeper A prefetch: NSTAGE=4, distance 3, CP_WAIT(2),
// uniform empty commits in the tail so group accounting never underflows.
// ---------------------------------------------------------------------------
__global__ void __launch_bounds__(GT) gemm_hmma_kernel(int lvl, int leaf, int c0,
                                                       int arow_off, int next_off,
                                                       int cin, int cout) {
    extern __shared__ char sm[];
    const uint32_t sb = smem_to_u32(sm);
    const int tid = threadIdx.x;
    const int wid = tid >> 5, lid = tid & 31;
    const int g = lid >> 2, q = lid & 3;
    const int half = wid & 1;            // column half (64 cols)
    const int stripe = wid >> 1;         // row stripe (32 rows)
    const int rowBase = blockIdx.y * 64;
    const int cb = blockIdx.x;           // colblk: 128 interleaved n

    const int lrow = (lid & 7) + ((lid >> 3) & 1) * 8;
    const int lkb  = (lid >> 4) * 16;

    float acc[2][8][4];
#pragma unroll
    for (int rf = 0; rf < 2; rf++)
#pragma unroll
        for (int i = 0; i < 8; i++)
#pragma unroll
            for (int k = 0; k < 4; k++) acc[rf][i][k] = 0.0f;

    const uint4* __restrict__ bsrc = g_wpack + (size_t)cb * (16 * 512)
                                   + (size_t)half * (4 * 32) + lid;

#define LOAD_A(ch) do {                                                           \
    uint32_t sb_ = sb + (uint32_t)((ch) % NSTAGE) * STAGE_BYTES;                  \
    _Pragma("unroll")                                                             \
    for (int i = tid; i < 256; i += GT) {                                         \
        int r = i >> 2, s = i & 3;                                                \
        uint32_t d = swz_addr(sb_, r, s * 16);                                    \
        const __half* srcp = g_ah + (size_t)(arow_off + rowBase + r) * KD         \
                           + (ch) * K_CHUNK + s * 8;                              \
        CP_ASYNC16(d, srcp);                                                      \
    }                                                                             \
    CP_COMMIT();                                                                  \
} while (0)

#define LOAD_B(breg, ch) do {                                                     \
    const uint4* __restrict__ bp_ = bsrc + (size_t)(ch) * 512;                    \
    _Pragma("unroll")                                                             \
    for (int ks_ = 0; ks_ < 2; ks_++)                                             \
        _Pragma("unroll")                                                         \
        for (int ntpl_ = 0; ntpl_ < 4; ntpl_++)                                   \
            (breg)[ks_ * 4 + ntpl_] = bp_[ks_ * 256 + ntpl_ * 32];                \
} while (0)

    // Prologue: 3 A-chunks in flight (distance 3).
    LOAD_A(c0);
    LOAD_A(c0 + 1);
    LOAD_A(c0 + 2);
    uint4 breg[8];
    LOAD_B(breg, c0);

    for (int ch = c0; ch < 16; ch++) {
        // Outstanding groups: {ch, ch+1, ch+2} (empties in tail keep count uniform).
        CP_WAIT(2);
        __syncthreads();
        if (ch + 3 < 16) { LOAD_A(ch + 3); } else { CP_COMMIT(); }

        uint32_t st = sb + (uint32_t)(ch % NSTAGE) * STAGE_BYTES;
#pragma unroll
        for (int ks = 0; ks < 2; ks++) {
            int kb = ks * 32;
            uint32_t af[2][4];
#pragma unroll
            for (int rf = 0; rf < 2; rf++) {
                int r = stripe * 32 + rf * 16 + lrow;
                LDSM_X4(af[rf], swz_addr(st, r, kb + lkb));
            }
#pragma unroll
            for (int ntpl = 0; ntpl < 4; ntpl++) {
                uint4 bb = breg[ks * 4 + ntpl];
#pragma unroll
                for (int rf = 0; rf < 2; rf++) {
                    MMA_F16(acc[rf][ntpl * 2],     af[rf][0], af[rf][1], af[rf][2], af[rf][3], bb.x, bb.y);
                    MMA_F16(acc[rf][ntpl * 2 + 1], af[rf][0], af[rf][1], af[rf][2], af[rf][3], bb.z, bb.w);
                }
            }
        }
        if (ch + 1 < 16) LOAD_B(breg, ch + 1);
    }
#undef LOAD_A
#undef LOAD_B

    // Fused epilogue: gates -> (h, c); sibling pair-sum via shfl_down(4);
    // even-g lanes write next level's A h-half (fp16) + c-sum (fp32).
    const bool evenq = ((q & 1) == 0);
    const float* bp = leaf ? g_biasleaf : g_bias;
    const float* csin = g_csum[cin];
    float* csout = g_csum[cout];
    const int jb = cb * 32 + half * 16 + (q >> 1);
    const bool geven = ((g & 1) == 0);
#pragma unroll
    for (int rf = 0; rf < 2; rf++) {
        const int m = rowBase + stripe * 32 + rf * 16 + g + ((lid & 1) ? 8 : 0);
        const float* csrow = csin + (size_t)m * 256;
        int m2 = 0;
        if (lvl > 0) {
            int b = m >> lvl;
            int n = m & ((1 << lvl) - 1);
            m2 = (b << (lvl - 1)) + (n >> 1);
        }
#pragma unroll
        for (int nt = 0; nt < 8; nt++) {
            float t0 = __shfl_xor_sync(0xffffffffu, acc[rf][nt][0], 1);
            float t1 = __shfl_xor_sync(0xffffffffu, acc[rf][nt][1], 1);
            float t2 = __shfl_xor_sync(0xffffffffu, acc[rf][nt][2], 1);
            float t3 = __shfl_xor_sync(0xffffffffu, acc[rf][nt][3], 1);
            float pf = evenq ? acc[rf][nt][0] : t2;
            float pi = evenq ? acc[rf][nt][1] : t3;
            float pu = evenq ? t0 : acc[rf][nt][2];
            float po = evenq ? t1 : acc[rf][nt][3];
            int j = jb + nt * 2;
            float f  = fast_sig (pf + bp[j]);
            float ig = fast_sig (pi + bp[256 + j]);
            float u  = fast_tanh(pu + bp[512 + j]);
            float o  = fast_sig (po + bp[768 + j]);
            float csum = leaf ? 2.0f * g_leaf_c[j] : csrow[j];
            float cn = ig * u + f * csum;
            float hn = o * fast_tanh(cn);
            if (lvl > 0) {
                float cnp = __shfl_down_sync(0xffffffffu, cn, 4);
                float hnp = __shfl_down_sync(0xffffffffu, hn, 4);
                if (geven) {
                    g_ah[(size_t)(next_off + m2) * KD + j] = __float2half(hn + hnp);
                    csout[(size_t)m2 * 256 + j] = cn + cnp;
                }
            } else {
                g_root[m * 256 + j] = hn;
            }
        }
    }
}

// ---------------------------------------------------------------------------
// Head MLP (tiny, fp32): out = act(A @ W^T + bias [+ g_y])
// ---------------------------------------------------------------------------
__global__ void head_kernel(const float* __restrict__ W, const float* __restrict__ bias,
                            int src, int dst, int addy, int act, float* __restrict__ out) {
    __shared__ float arow[256];
    int b = blockIdx.x;
    int j = threadIdx.x;
    const float* A = (src == 0) ? g_root : (src == 1) ? g_t : g_z;
    arow[j] = A[b * 256 + j];
    __syncthreads();
    float acc = bias[j];
    const float* wr = W + j * 256;
#pragma unroll 8
    for (int k = 0; k < 256; k++) acc += arow[k] * wr[k];
    if (addy) acc += g_y[b * 256 + j];
    if (act == 1) acc = fast_tanh(acc);
    else if (act == 2) acc = fmaxf(acc, 0.0f);
    float* O = (dst == 0) ? g_y : (dst == 1) ? g_t : (dst == 2) ? g_z : out;
    O[b * 256 + j] = acc;
}

// ---------------------------------------------------------------------------
extern "C" void kernel_launch(void* const* d_in, const int* in_sizes, int n_in,
                              void* d_out, int out_size) {
    const float* embed = (const float*)d_in[0];
    const float* Wf  = (const float*)d_in[1];
    const float* bf  = (const float*)d_in[2];
    const float* b_f = (const float*)d_in[3];
    const float* Wi  = (const float*)d_in[4];
    const float* bi  = (const float*)d_in[5];
    const float* b_i = (const float*)d_in[6];
    const float* Wu  = (const float*)d_in[7];
    const float* bu  = (const float*)d_in[8];
    const float* b_u = (const float*)d_in[9];
    const float* Wo  = (const float*)d_in[10];
    const float* bo  = (const float*)d_in[11];
    const float* b_o = (const float*)d_in[12];
    const float* W1  = (const float*)d_in[13];
    const float* bl1 = (const float*)d_in[14];
    const float* W2  = (const float*)d_in[15];
    const float* bl2 = (const float*)d_in[16];
    const float* W3  = (const float*)d_in[17];
    const float* bl3 = (const float*)d_in[18];
    const float* W4  = (const float*)d_in[19];
    const float* bl4 = (const float*)d_in[20];
    float* out = (float*)d_out;

    leaf_bias_kernel<<<1, 256>>>(bf, b_f, bi, b_i, bu, b_u, bo, b_o);      // 0
    leafdot_kernel<<<4, 256>>>(Wf, Wi, Wu, Wo);                            // 1
    setup_kernel<<<256 + (TOTROWS * 64 + 255) / 256, 256>>>(embed, Wf, Wi, Wu, Wo); // 2

    for (int l = 8; l >= 0; --l) {
        int M = Bdim << l;
        int leaf = (l == 8);
        int arow_off = 65536 - (256 << l);
        int next_off = (l > 0) ? (65536 - (128 << l)) : 0;
        int cout = (8 - l) & 1;
        int cin = cout ^ 1;
        gemm_hmma_kernel<<<dim3(8, M / 64), GT, SMEM_SZ>>>(
            l, leaf, leaf ? 8 : 0, arow_off, next_off, cin, cout);
    }

    head_kernel<<<128, 256>>>(W1, bl1, 0, 0, 0, 1, out);  // y  = tanh(hr @ W1^T + bl1)
    head_kernel<<<128, 256>>>(W2, bl2, 0, 1, 0, 2, out);  // t  = relu(hr @ W2^T + bl2)
    head_kernel<<<128, 256>>>(W3, bl3, 1, 2, 1, 0, out);  // z  = t @ W3^T + bl3 + y
    head_kernel<<<128, 256>>>(W4, bl4, 2, 3, 0, 2, out);  // out = relu(z @ W4^T + bl4)
}

// round 15
// speedup vs baseline: 1.2752x; 1.0442x over previous
#include <cuda_runtime.h>
#include <cuda_fp16.h>
#include <math.h>
#include <stdint.h>

// Problem constants
#define Bdim 128
#define NN   1023
#define Xd   256
#define Hd   256
#define KD   512     // H + X
#define GD   1024    // 4 gates * H
#define TOTROWS 65408          // sum over levels of 128*2^l, l=0..8
// A row offset of level l: OFF(l) = 65536 - (256<<l)  (l=8 -> 0)

// ---------------------------------------------------------------------------
// Static device scratch (allocation-free rule)
// ---------------------------------------------------------------------------
__device__ __half g_ah[65536 * 512];         // A for ALL levels (64 MB)
__device__ float g_csum[2][16384 * 256];     // ping-pong c-pair-sums
__device__ float g_root[Bdim * Hd];          // root hidden state (fp32)
__device__ uint4 g_wpack[8*16*2*8*32];       // packed W, 1 MB
__device__ float g_leaf_c[Hd];
__device__ float g_leaf_h[Hd];
__device__ float g_bias[GD];                 // gate-major: [f i u o] x 256
__device__ float g_biasleaf[GD];
__device__ float g_y[Bdim*Hd];
__device__ float g_t[Bdim*Hd];
__device__ float g_z[Bdim*Hd];

// Exact (setup-only) sigmoid
__device__ __forceinline__ float sigmoidf_(float x) { return 1.0f / (1.0f + expf(-x)); }

// Fast MUFU-based activations (ex2.approx + rcp.approx, rel err ~1e-6)
__device__ __forceinline__ float fast_sig(float x) {
    float e;
    asm("ex2.approx.f32 %0, %1;" : "=f"(e) : "f"(x * -1.4426950408889634f));
    float r;
    asm("rcp.approx.f32 %0, %1;" : "=f"(r) : "f"(1.0f + e));
    return r;
}
__device__ __forceinline__ float fast_tanh(float x) {
    return fmaf(2.0f, fast_sig(2.0f * x), -1.0f);
}

__device__ __forceinline__ uint32_t smem_to_u32(const void* p) {
    uint32_t a;
    asm("{ .reg .u64 t; cvta.to.shared.u64 t, %1; cvt.u32.u64 %0, t; }" : "=r"(a) : "l"(p));
    return a;
}
#define LDSM_X4(r, addr) \
    asm volatile("ldmatrix.sync.aligned.m8n8.x4.shared.b16 {%0,%1,%2,%3}, [%4];" \
        : "=r"((r)[0]), "=r"((r)[1]), "=r"((r)[2]), "=r"((r)[3]) : "r"(addr))
#define CP_ASYNC16(daddr, src) \
    asm volatile("cp.async.cg.shared.global [%0], [%1], 16;" :: "r"(daddr), "l"(src) : "memory")
#define CP_COMMIT() asm volatile("cp.async.commit_group;" ::: "memory")
#define CP_WAIT(n)  asm volatile("cp.async.wait_group %0;" :: "n"(n) : "memory")

#define MMA_F16(d, a0, a1, a2, a3, b0, b1) \
    asm volatile("mma.sync.aligned.m16n8k16.row.col.f32.f16.f16.f32 " \
        "{%0,%1,%2,%3}, {%4,%5,%6,%7}, {%8,%9}, {%0,%1,%2,%3};" \
        : "+f"((d)[0]), "+f"((d)[1]), "+f"((d)[2]), "+f"((d)[3]) \
        : "r"(a0), "r"(a1), "r"(a2), "r"(a3), "r"(b0), "r"(b1))

// GEMM geometry: CTA = 64 rows x 128 interleaved cols, 128 threads (4 warps)
#define GT 128
#define K_CHUNK 32
#define STAGE_BYTES 4096
#define NSTAGE 4
#define SMEM_SZ (NSTAGE * STAGE_BYTES)  // 16384

__device__ __forceinline__ uint32_t swz_addr(uint32_t base, int row, int kb) {
    return base + row * 64 + (((((uint32_t)kb >> 4) ^ ((uint32_t)row >> 1)) & 3u) << 4) + (kb & 15);
}

__device__ __forceinline__ uint32_t pk_h2(float a, float b) {
    __half2 t = __floats2half2_rn(a, b);
    return *reinterpret_cast<uint32_t*>(&t);
}

// ---------------------------------------------------------------------------
// k0: leaf vectors + gate-major combined bias (exact libm; runs once)
// ---------------------------------------------------------------------------
__global__ void leaf_bias_kernel(const float* __restrict__ bf, const float* __restrict__ b_f,
                                 const float* __restrict__ bi, const float* __restrict__ b_i,
                                 const float* __restrict__ bu, const float* __restrict__ b_u,
                                 const float* __restrict__ bo, const float* __restrict__ b_o) {
    int j = threadIdx.x;
    float ig = sigmoidf_(bi[j] + b_i[j]);
    float ug = tanhf(bu[j] + b_u[j]);
    float cl = ig * ug;
    g_leaf_c[j] = cl;
    g_leaf_h[j] = sigmoidf_(bo[j] + b_o[j]) * tanhf(cl);
    g_bias[j]       = bf[j] + b_f[j];
    g_bias[256 + j] = bi[j] + b_i[j];
    g_bias[512 + j] = bu[j] + b_u[j];
    g_bias[768 + j] = bo[j] + b_o[j];
}

// ---------------------------------------------------------------------------
// k1: leaf bias fold (fp32 exact)
// ---------------------------------------------------------------------------
__global__ void leafdot_kernel(const float* __restrict__ Wf, const float* __restrict__ Wi,
                               const float* __restrict__ Wu, const float* __restrict__ Wo) {
    __shared__ float lh[256];
    int t = threadIdx.x;
    lh[t] = 2.0f * g_leaf_h[t];
    __syncthreads();
    int n = blockIdx.x * 256 + t;     // 0..1023
    int j = n >> 2, gate = n & 3;
    const float* W = (gate == 0) ? Wf : (gate == 1) ? Wi : (gate == 2) ? Wu : Wo;
    const float* wr = W + (size_t)j * 512;
    float acc = 0.0f;
#pragma unroll 8
    for (int k = 0; k < 256; k++) acc += wr[k] * lh[k];
    g_biasleaf[gate * 256 + j] = g_bias[gate * 256 + j] + acc;
}

// ---------------------------------------------------------------------------
// k2: fused convert_w (blocks 0..255) + embed halves for ALL levels
// ---------------------------------------------------------------------------
__device__ void convert_w_body(int bid, int t,
                               const float* Wf, const float* Wi,
                               const float* Wu, const float* Wo) {
    int idx = bid * 256 + t;   // 0 .. 65535
    int lane = idx & 31;
    int ntp  = (idx >> 5) & 7;
    int ks   = (idx >> 8) & 1;
    int ch   = (idx >> 9) & 15;
    int cb   = idx >> 13;
    int tig = lane & 3;
    int k0 = ch * 32 + ks * 16 + tig * 2;
    uint4 v;
    uint32_t* vv = (uint32_t*)&v;
#pragma unroll
    for (int half = 0; half < 2; half++) {
        int nt = ntp * 2 + half;
        int n = cb * 128 + nt * 8 + (lane >> 2);    // interleaved n = j*4+gate
        int j = n >> 2, gate = n & 3;
        const float* W = (gate == 0) ? Wf : (gate == 1) ? Wi : (gate == 2) ? Wu : Wo;
        const float* wr = W + (size_t)j * 512;
        vv[half * 2]     = pk_h2(wr[k0],     wr[k0 + 1]);
        vv[half * 2 + 1] = pk_h2(wr[k0 + 8], wr[k0 + 9]);
    }
    g_wpack[idx] = v;
}

__device__ void embed_body(int bid, int t, const float* embed) {
    int idx = bid * 256 + t;            // 0 .. TOTROWS*64-1
    if (idx >= TOTROWS * 64) return;
    int r = idx >> 6, qq = idx & 63;
    unsigned u = 65536u - (unsigned)r;
    int l = 31 - __clz((u - 1) >> 7);   // level of row r
    int m = r - (65536 - (256 << l));
    int b = m >> l;
    int n = m & ((1 << l) - 1);
    int node0 = (2 << l) - 1 + 2 * n;
    const float4* e0 = (const float4*)(embed + ((size_t)b * NN + node0) * Xd) + qq;
    const float4* e1 = (const float4*)(embed + ((size_t)b * NN + node0 + 1) * Xd) + qq;
    float4 a = *e0, c = *e1;
    size_t p = (size_t)r * 256 + 128 + (size_t)qq * 2;
    ((__half2*)g_ah)[p]     = __floats2half2_rn(a.x + c.x, a.y + c.y);
    ((__half2*)g_ah)[p + 1] = __floats2half2_rn(a.z + c.z, a.w + c.w);
}

__global__ void setup_kernel(const float* __restrict__ embed,
                             const float* __restrict__ Wf, const float* __restrict__ Wi,
                             const float* __restrict__ Wu, const float* __restrict__ Wo) {
    int bid = blockIdx.x;
    if (bid < 256) convert_w_body(bid, threadIdx.x, Wf, Wi, Wu, Wo);
    else           embed_body(bid - 256, threadIdx.x, embed);
}

// ---------------------------------------------------------------------------
// HMMA GEMM + fused epilogue with smem-staged COALESCED stores.
// Mainloop identical to R14 (best known).
// ---------------------------------------------------------------------------
__global__ void __launch_bounds__(GT) gemm_hmma_kernel(int lvl, int leaf, int c0,
                                                       int arow_off, int next_off,
                                                       int cin, int cout) {
    extern __shared__ char sm[];
    const uint32_t sb = smem_to_u32(sm);
    const int tid = threadIdx.x;
    const int wid = tid >> 5, lid = tid & 31;
    const int g = lid >> 2, q = lid & 3;
    const int half = wid & 1;            // column half (64 cols)
    const int stripe = wid >> 1;         // row stripe (32 rows)
    const int rowBase = blockIdx.y * 64;
    const int cb = blockIdx.x;           // colblk: 128 interleaved n

    const int lrow = (lid & 7) + ((lid >> 3) & 1) * 8;
    const int lkb  = (lid >> 4) * 16;

    float acc[2][8][4];
#pragma unroll
    for (int rf = 0; rf < 2; rf++)
#pragma unroll
        for (int i = 0; i < 8; i++)
#pragma unroll
            for (int k = 0; k < 4; k++) acc[rf][i][k] = 0.0f;

    const uint4* __restrict__ bsrc = g_wpack + (size_t)cb * (16 * 512)
                                   + (size_t)half * (4 * 32) + lid;

#define LOAD_A(ch) do {                                                           \
    uint32_t sb_ = sb + (uint32_t)((ch) % NSTAGE) * STAGE_BYTES;                  \
    _Pragma("unroll")                                                             \
    for (int i = tid; i < 256; i += GT) {                                         \
        int r = i >> 2, s = i & 3;                                                \
        uint32_t d = swz_addr(sb_, r, s * 16);                                    \
        const __half* srcp = g_ah + (size_t)(arow_off + rowBase + r) * KD         \
                           + (ch) * K_CHUNK + s * 8;                              \
        CP_ASYNC16(d, srcp);                                                      \
    }                                                                             \
    CP_COMMIT();                                                                  \
} while (0)

#define LOAD_B(breg, ch) do {                                                     \
    const uint4* __restrict__ bp_ = bsrc + (size_t)(ch) * 512;                    \
    _Pragma("unroll")                                                             \
    for (int ks_ = 0; ks_ < 2; ks_++)                                             \
        _Pragma("unroll")                                                         \
        for (int ntpl_ = 0; ntpl_ < 4; ntpl_++)                                   \
            (breg)[ks_ * 4 + ntpl_] = bp_[ks_ * 256 + ntpl_ * 32];                \
} while (0)

    // Prologue: 3 A-chunks in flight (distance 3).
    LOAD_A(c0);
    LOAD_A(c0 + 1);
    LOAD_A(c0 + 2);
    uint4 breg[8];
    LOAD_B(breg, c0);

    for (int ch = c0; ch < 16; ch++) {
        CP_WAIT(2);
        __syncthreads();
        if (ch + 3 < 16) { LOAD_A(ch + 3); } else { CP_COMMIT(); }

        uint32_t st = sb + (uint32_t)(ch % NSTAGE) * STAGE_BYTES;
#pragma unroll
        for (int ks = 0; ks < 2; ks++) {
            int kb = ks * 32;
            uint32_t af[2][4];
#pragma unroll
            for (int rf = 0; rf < 2; rf++) {
                int r = stripe * 32 + rf * 16 + lrow;
                LDSM_X4(af[rf], swz_addr(st, r, kb + lkb));
            }
#pragma unroll
            for (int ntpl = 0; ntpl < 4; ntpl++) {
                uint4 bb = breg[ks * 4 + ntpl];
#pragma unroll
                for (int rf = 0; rf < 2; rf++) {
                    MMA_F16(acc[rf][ntpl * 2],     af[rf][0], af[rf][1], af[rf][2], af[rf][3], bb.x, bb.y);
                    MMA_F16(acc[rf][ntpl * 2 + 1], af[rf][0], af[rf][1], af[rf][2], af[rf][3], bb.z, bb.w);
                }
            }
        }
        if (ch + 1 < 16) LOAD_B(breg, ch + 1);
    }
#undef LOAD_A
#undef LOAD_B

    // Fused epilogue: gates -> (h, c); sibling pair-sum via shfl_down(4).
    // Outputs staged in smem (stages 0/1: safe — last used at chunk 13, and
    // every warp here passed the chunk-15 barrier), then coalesced copyout.
    __half* ah_s = (__half*)sm;                 // [32][32] fp16, 2 KB
    float*  cs_s = (float*)(sm + 2048);         // [32][32] fp32, 4 KB
    const bool evenq = ((q & 1) == 0);
    const float* bp = leaf ? g_biasleaf : g_bias;
    const float* csin = g_csum[cin];
    const int jb = cb * 32 + half * 16 + (q >> 1);
    const int jloc = half * 16 + (q >> 1);
    const bool geven = ((g & 1) == 0);
#pragma unroll
    for (int rf = 0; rf < 2; rf++) {
        const int lm = stripe * 32 + rf * 16 + g + ((lid & 1) ? 8 : 0);
        const int m = rowBase + lm;
        const float* csrow = csin + (size_t)m * 256;
#pragma unroll
        for (int nt = 0; nt < 8; nt++) {
            float t0 = __shfl_xor_sync(0xffffffffu, acc[rf][nt][0], 1);
            float t1 = __shfl_xor_sync(0xffffffffu, acc[rf][nt][1], 1);
            float t2 = __shfl_xor_sync(0xffffffffu, acc[rf][nt][2], 1);
            float t3 = __shfl_xor_sync(0xffffffffu, acc[rf][nt][3], 1);
            float pf = evenq ? acc[rf][nt][0] : t2;
            float pi = evenq ? acc[rf][nt][1] : t3;
            float pu = evenq ? t0 : acc[rf][nt][2];
            float po = evenq ? t1 : acc[rf][nt][3];
            int j = jb + nt * 2;
            float f  = fast_sig (pf + bp[j]);
            float ig = fast_sig (pi + bp[256 + j]);
            float u  = fast_tanh(pu + bp[512 + j]);
            float o  = fast_sig (po + bp[768 + j]);
            float csum = leaf ? 2.0f * g_leaf_c[j] : csrow[j];
            float cn = ig * u + f * csum;
            float hn = o * fast_tanh(cn);
            if (lvl > 0) {
                float cnp = __shfl_down_sync(0xffffffffu, cn, 4);
                float hnp = __shfl_down_sync(0xffffffffu, hn, 4);
                if (geven) {
                    int r2 = lm >> 1;               // 0..31 (lm is even here)
                    int jl = jloc + nt * 2;         // 0..31
                    ah_s[r2 * 32 + jl] = __float2half(hn + hnp);
                    cs_s[r2 * 32 + jl] = cn + cnp;
                }
            } else {
                g_root[m * 256 + j] = hn;
            }
        }
    }

    if (lvl > 0) {
        __syncthreads();
        float* csout = g_csum[cout];
        const int mask = (1 << lvl) - 1;
        // g_ah copyout: 32 rows x 64 B; one uint4 per thread.
        {
            int r2 = tid >> 2, qd = tid & 3;
            int mloc = rowBase + 2 * r2;
            int b = mloc >> lvl, n = mloc & mask;
            int m2 = (b << (lvl - 1)) + (n >> 1);
            uint4 v = *(const uint4*)(ah_s + r2 * 32 + qd * 8);
            *(uint4*)(g_ah + (size_t)(next_off + m2) * KD + cb * 32 + qd * 8) = v;
        }
        // csum copyout: 32 rows x 128 B; two float4 per thread.
#pragma unroll
        for (int ii = 0; ii < 2; ii++) {
            int idx = tid * 2 + ii;
            int r2 = idx >> 3, qd = idx & 7;
            int mloc = rowBase + 2 * r2;
            int b = mloc >> lvl, n = mloc & mask;
            int m2 = (b << (lvl - 1)) + (n >> 1);
            float4 v = *(const float4*)(cs_s + r2 * 32 + qd * 4);
            *(float4*)(csout + (size_t)m2 * 256 + cb * 32 + qd * 4) = v;
        }
    }
}

// ---------------------------------------------------------------------------
// Head MLP (tiny, fp32): out = act(A @ W^T + bias [+ g_y])
// ---------------------------------------------------------------------------
__global__ void head_kernel(const float* __restrict__ W, const float* __restrict__ bias,
                            int src, int dst, int addy, int act, float* __restrict__ out) {
    __shared__ float arow[256];
    int b = blockIdx.x;
    int j = threadIdx.x;
    const float* A = (src == 0) ? g_root : (src == 1) ? g_t : g_z;
    arow[j] = A[b * 256 + j];
    __syncthreads();
    float acc = bias[j];
    const float* wr = W + j * 256;
#pragma unroll 8
    for (int k = 0; k < 256; k++) acc += arow[k] * wr[k];
    if (addy) acc += g_y[b * 256 + j];
    if (act == 1) acc = fast_tanh(acc);
    else if (act == 2) acc = fmaxf(acc, 0.0f);
    float* O = (dst == 0) ? g_y : (dst == 1) ? g_t : (dst == 2) ? g_z : out;
    O[b * 256 + j] = acc;
}

// ---------------------------------------------------------------------------
extern "C" void kernel_launch(void* const* d_in, const int* in_sizes, int n_in,
                              void* d_out, int out_size) {
    const float* embed = (const float*)d_in[0];
    const float* Wf  = (const float*)d_in[1];
    const float* bf  = (const float*)d_in[2];
    const float* b_f = (const float*)d_in[3];
    const float* Wi  = (const float*)d_in[4];
    const float* bi  = (const float*)d_in[5];
    const float* b_i = (const float*)d_in[6];
    const float* Wu  = (const float*)d_in[7];
    const float* bu  = (const float*)d_in[8];
    const float* b_u = (const float*)d_in[9];
    const float* Wo  = (const float*)d_in[10];
    const float* bo  = (const float*)d_in[11];
    const float* b_o = (const float*)d_in[12];
    const float* W1  = (const float*)d_in[13];
    const float* bl1 = (const float*)d_in[14];
    const float* W2  = (const float*)d_in[15];
    const float* bl2 = (const float*)d_in[16];
    const float* W3  = (const float*)d_in[17];
    const float* bl3 = (const float*)d_in[18];
    const float* W4  = (const float*)d_in[19];
    const float* bl4 = (const float*)d_in[20];
    float* out = (float*)d_out;

    leaf_bias_kernel<<<1, 256>>>(bf, b_f, bi, b_i, bu, b_u, bo, b_o);      // 0
    leafdot_kernel<<<4, 256>>>(Wf, Wi, Wu, Wo);                            // 1
    setup_kernel<<<256 + (TOTROWS * 64 + 255) / 256, 256>>>(embed, Wf, Wi, Wu, Wo); // 2

    for (int l = 8; l >= 0; --l) {
        int M = Bdim << l;
        int leaf = (l == 8);
        int arow_off = 65536 - (256 << l);
        int next_off = (l > 0) ? (65536 - (128 << l)) : 0;
        int cout = (8 - l) & 1;
        int cin = cout ^ 1;
        gemm_hmma_kernel<<<dim3(8, M / 64), GT, SMEM_SZ>>>(
            l, leaf, leaf ? 8 : 0, arow_off, next_off, cin, cout);
    }

    head_kernel<<<128, 256>>>(W1, bl1, 0, 0, 0, 1, out);  // y  = tanh(hr @ W1^T + bl1)
    head_kernel<<<128, 256>>>(W2, bl2, 0, 1, 0, 2, out);  // t  = relu(hr @ W2^T + bl2)
    head_kernel<<<128, 256>>>(W3, bl3, 1, 2, 1, 0, out);  // z  = t @ W3^T + bl3 + y
    head_kernel<<<128, 256>>>(W4, bl4, 2, 3, 0, 2, out);  // out = relu(z @ W4^T + bl4)
}